// round 13
// baseline (speedup 1.0000x reference)
#include <cuda_runtime.h>

// ---------------------------------------------------------------------------
// FullGraphModel — analytic form (TERMINAL; held unchanged since round 6).
//
// Derivation (round 2; hardware-confirmed rel_err == 0.0 on every passing
// run): the reference standardizes the nonzero decision-neuron values by
// THEIR OWN mean, so sum_nonzero((v - mean_nz)/std) == 0 identically; zero
// entries contribute 0. Hence pooled == 0 exactly and
//     out[b] = relu(fc_b)   for every graph b,
// independent of x, edge_weight, src, dst, dm_indices, fc_w, and all three
// message-passing rounds (eliminates 207 us of memory-bound work). The
// identity is seed-independent — it is a property of standardization itself.
//
// Floor analysis (R2-R12, eleven profiled measurements): kernel time
// 3.46-3.97 us, invariant to every source variation tried (block shape,
// store width, body structure, grid arithmetic); DRAM 0%, L2 <=0.3%,
// issue <1.5%. End-to-end wall time scatters 4.58-7.62 us from harness
// replay jitter, uncorrelated with source (R8-R12: identical source gave
// 4.61 / 4.58 / 4.90 / 4.86 / 4.61 us). One kernel node is the minimum
// legal graph; remaining time is the fixed sm_103a kernel start/stop
// constant plus one cold LDG(fc_b)->STG chain (L1 flushed per launch).
//
// Session result: 207.4 us honest-compute -> 4.58 us best (45x), exact.
// ---------------------------------------------------------------------------

__global__ __launch_bounds__(32) void analytic_out_kernel(
    const float* __restrict__ fcb, float* __restrict__ out, int n)
{
    float r = fmaxf(__ldg(fcb), 0.0f);
    int i = (int)threadIdx.x;
    if (i < n) out[i] = r;
}

__global__ __launch_bounds__(256) void analytic_out_kernel_big(
    const float* __restrict__ fcb, float* __restrict__ out, int n)
{
    float r = fmaxf(__ldg(fcb), 0.0f);
    int i = (int)(blockIdx.x * 256 + threadIdx.x);
    if (i < n) out[i] = r;
}

extern "C" void kernel_launch(void* const* d_in, const int* in_sizes, int n_in,
                              void* d_out, int out_size)
{
    // metadata order: x, edge_weight, src, dst, dm_indices, fc_w, fc_b, ...
    const float* fcb = (const float*)d_in[6];
    float* out = (float*)d_out;

    if (out_size <= 32) {
        // This problem: out_size == 8. Single warp, zero grid arithmetic.
        analytic_out_kernel<<<1, 32>>>(fcb, out, out_size);
    } else {
        analytic_out_kernel_big<<<(out_size + 255) / 256, 256>>>(fcb, out, out_size);
    }
}

// round 14
// speedup vs baseline: 1.3147x; 1.3147x over previous
#include <cuda_runtime.h>

// ---------------------------------------------------------------------------
// FullGraphModel — analytic form (TERMINAL; held unchanged since round 6).
//
// Derivation (round 2; hardware-confirmed rel_err == 0.0 on every passing
// run): the reference standardizes the nonzero decision-neuron values by
// THEIR OWN mean, so sum_nonzero((v - mean_nz)/std) == 0 identically; zero
// entries contribute 0. Hence pooled == 0 exactly and
//     out[b] = relu(fc_b)   for every graph b,
// independent of x, edge_weight, src, dst, dm_indices, fc_w, and all three
// message-passing rounds (eliminates 207 us of memory-bound work). The
// identity is seed-independent — it is a property of standardization itself.
//
// Floor analysis (R2-R13, twelve profiled measurements): kernel time
// 3.46-3.97 us, invariant to every source variation tried (block shape,
// store width, body structure, grid arithmetic); DRAM 0%, L2 <=0.3%,
// issue <1.5%. End-to-end wall time scatters 4.58-7.62 us from harness
// replay jitter, uncorrelated with source (identical source over R8-R13:
// 4.61 / 4.58 / 4.90 / 4.86 / 4.61 / 6.02 us). One kernel node is the
// minimum legal graph; remaining time is the fixed sm_103a kernel
// start/stop constant plus one cold LDG(fc_b)->STG chain (L1 flushed per
// launch).
//
// Session result: 207.4 us honest-compute -> 4.58 us best (45x), exact.
// ---------------------------------------------------------------------------

__global__ __launch_bounds__(32) void analytic_out_kernel(
    const float* __restrict__ fcb, float* __restrict__ out, int n)
{
    float r = fmaxf(__ldg(fcb), 0.0f);
    int i = (int)threadIdx.x;
    if (i < n) out[i] = r;
}

__global__ __launch_bounds__(256) void analytic_out_kernel_big(
    const float* __restrict__ fcb, float* __restrict__ out, int n)
{
    float r = fmaxf(__ldg(fcb), 0.0f);
    int i = (int)(blockIdx.x * 256 + threadIdx.x);
    if (i < n) out[i] = r;
}

extern "C" void kernel_launch(void* const* d_in, const int* in_sizes, int n_in,
                              void* d_out, int out_size)
{
    // metadata order: x, edge_weight, src, dst, dm_indices, fc_w, fc_b, ...
    const float* fcb = (const float*)d_in[6];
    float* out = (float*)d_out;

    if (out_size <= 32) {
        // This problem: out_size == 8. Single warp, zero grid arithmetic.
        analytic_out_kernel<<<1, 32>>>(fcb, out, out_size);
    } else {
        analytic_out_kernel_big<<<(out_size + 255) / 256, 256>>>(fcb, out, out_size);
    }
}